// round 10
// baseline (speedup 1.0000x reference)
#include <cuda_runtime.h>
#include <cstdint>

#define B  8
#define N  4096
#define F  128
#define GS 1024

// Scratch
__device__ unsigned int g_keys[B * N];    // monotone-mapped values
__device__ unsigned int g_hist[B * 256];  // top-8-bit histogram (re-zeroed by select)
__device__ int          g_idx[B * GS];    // final top-k indices, jax order

__device__ __forceinline__ unsigned int monot(float v) {
    unsigned int u = __float_as_uint(v);
    return (u & 0x80000000u) ? ~u : (u | 0x80000000u); // bigger float -> bigger uint
}

// ---------------------------------------------------------------------------
// K1: chip-wide extract + per-batch 256-bin histogram of the top 8 key bits.
// ---------------------------------------------------------------------------
__global__ __launch_bounds__(256) void extract_hist_kernel(const float* __restrict__ x)
{
    __shared__ unsigned int h[256];
    const int tid = threadIdx.x;
    h[tid] = 0;
    __syncthreads();

    const int i = blockIdx.x * 256 + tid;   // 0 .. B*N-1
    const int b = i >> 12;
    unsigned int u = monot(__ldcs(&x[(size_t)i * F + (F - 1)]));
    g_keys[i] = u;
    atomicAdd(&h[u >> 24], 1u);
    __syncthreads();

    unsigned int c = h[tid];
    if (c) atomicAdd(&g_hist[b * 256 + tid], c);
}

// ---------------------------------------------------------------------------
// K2: per-batch select + bucketed rank, fused. 8 CTAs x 1024 thr.
// composite = (u << 12) | (4095 - i): larger == earlier in jax order; unique.
// rank(key) = suffix_offset(bin(key)) + #greater among its ~16 bucket-mates.
// ---------------------------------------------------------------------------
__device__ __forceinline__ void scan_hist(const unsigned int* hist, unsigned int need,
                                          unsigned int* s_bin, unsigned int* s_above)
{
    const int tid = threadIdx.x;
    if (tid < 32) {
        unsigned int sum = 0;
        #pragma unroll
        for (int j = 0; j < 8; ++j) sum += hist[tid * 8 + j];
        unsigned int acc = sum;
        #pragma unroll
        for (int off = 1; off < 32; off <<= 1) {
            unsigned int t = __shfl_down_sync(0xFFFFFFFFu, acc, off);
            if (tid + off < 32) acc += t;
        }
        unsigned int running = acc - sum;      // strictly above my 8-bin group
        #pragma unroll
        for (int j = 7; j >= 0; --j) {
            unsigned int c = hist[tid * 8 + j];
            if (running < need && need <= running + c) {
                *s_bin = (unsigned int)(tid * 8 + j);
                *s_above = running;
            }
            running += c;
        }
    }
}

__global__ __launch_bounds__(1024) void select_rank_kernel()
{
    __shared__ unsigned long long cand[N];      // 32 KB (worst-case bin)
    __shared__ unsigned long long stage[GS];    // 8 KB, bin-grouped selected keys
    __shared__ unsigned int h1[256];            // preserved pass-1 histogram
    __shared__ unsigned int hw[256];            // working histogram
    __shared__ unsigned int off[256];           // suffix offsets (selected-set)
    __shared__ unsigned int bpos[256];          // bucket fill counters
    __shared__ unsigned int s_bin, s_above, s_m;

    const int b   = blockIdx.x;
    const int tid = threadIdx.x;

    if (tid < 256) {
        h1[tid] = g_hist[b * 256 + tid];
        g_hist[b * 256 + tid] = 0;              // re-zero for next replay
        bpos[tid] = 0;
    }
    if (tid == 0) s_m = 0;
    __syncthreads();

    scan_hist(h1, GS, &s_bin, &s_above);
    __syncthreads();
    const unsigned int bin1  = s_bin;
    const unsigned int need1 = GS - s_above;
    unsigned int need = need1;

    // Build composites (coalesced), compact threshold-bin candidates
    unsigned long long comp[4];
    #pragma unroll
    for (int l = 0; l < 4; ++l) {
        int i = l * 1024 + tid;
        unsigned int u = g_keys[b * N + i];
        comp[l] = ((unsigned long long)u << 12) | (unsigned int)(N - 1 - i);
        if ((u >> 24) == bin1) {
            unsigned int p = atomicAdd(&s_m, 1u);
            cand[p] = comp[l];
        }
    }

    // Suffix offsets over full histogram: off[v] = sum_{v' > v} h1[v']
    if (tid < 32) {
        unsigned int sum = 0;
        #pragma unroll
        for (int j = 0; j < 8; ++j) sum += h1[tid * 8 + j];
        unsigned int acc = sum;
        #pragma unroll
        for (int o = 1; o < 32; o <<= 1) {
            unsigned int t = __shfl_down_sync(0xFFFFFFFFu, acc, o);
            if (tid + o < 32) acc += t;
        }
        unsigned int running = acc - sum;   // strictly above my group
        #pragma unroll
        for (int j = 7; j >= 0; --j) {
            off[tid * 8 + j] = running;
            running += h1[tid * 8 + j];
        }
    }
    __syncthreads();
    const unsigned int m = s_m;

    // 5-pass radix on candidates -> exact GS-th largest composite
    unsigned long long prefix = (unsigned long long)bin1 << 36;
    unsigned long long pmask  = 0xFFull << 36;

    #pragma unroll
    for (int pass = 0; pass < 5; ++pass) {
        const int          shift = (pass < 4) ? (28 - 8 * pass) : 0;
        const unsigned int dmask = (pass < 4) ? 0xFFu : 0xFu;

        if (tid < 256) hw[tid] = 0;
        __syncthreads();
        for (unsigned int idx = tid; idx < m; idx += 1024) {
            unsigned long long k = cand[idx];
            if ((k & pmask) == prefix)
                atomicAdd(&hw[(unsigned int)(k >> shift) & dmask], 1u);
        }
        __syncthreads();
        scan_hist(hw, need, &s_bin, &s_above);
        __syncthreads();
        prefix |= ((unsigned long long)s_bin) << shift;
        pmask  |= ((unsigned long long)dmask) << shift;
        need   -= s_above;
        __syncthreads();
    }
    // Selected set: composite >= prefix (exactly GS keys, all bins >= bin1).

    // Stage selected keys grouped by bin: bin v occupies [off[v], off[v]+cnt)
    #pragma unroll
    for (int l = 0; l < 4; ++l) {
        if (comp[l] >= prefix) {
            unsigned int v = (unsigned int)(comp[l] >> 36);
            unsigned int p = off[v] + atomicAdd(&bpos[v], 1u);
            stage[p] = comp[l];
        }
    }
    __syncthreads();

    // Rank within bucket (avg ~16 mates), write final ordered index
    {
        unsigned long long k = stage[tid];
        unsigned int v     = (unsigned int)(k >> 36);
        unsigned int start = off[v];
        unsigned int cnt   = (v == bin1) ? need1 : h1[v];
        unsigned int r     = 0;
        for (unsigned int j = start; j < start + cnt; ++j)
            r += (stage[j] > k);
        g_idx[b * GS + start + r] = (N - 1) - (int)(k & 0xFFFull);
    }
}

// ---------------------------------------------------------------------------
// K3 (R8-proven shape): one CTA per output row (b, i).
//   - coalesced float4 streaming load of A[b, idx[i], :] (16KB) into smem
//   - paired smem gather (LDS.64 idx + 2 LDS + STG.64) -> At2 row
//   - warp 0 copies x[b, idx[i], :] (512B) -> xg row
// ---------------------------------------------------------------------------
__global__ __launch_bounds__(512) void gather_kernel(const float* __restrict__ A,
                                                     const float* __restrict__ x,
                                                     float* __restrict__ out)
{
    __shared__ float row[N];                    // 16 KB
    __shared__ __align__(8) int sidx[GS];       // 4 KB

    const int bi  = blockIdx.x;
    const int b   = bi >> 10;
    const int i   = bi & (GS - 1);
    const int tid = threadIdx.x;

    const int ri = g_idx[b * GS + i];

    const float4* arow = (const float4*)(A + ((size_t)b * N + ri) * N);
    float4* rowv = (float4*)row;
    #pragma unroll
    for (int t = tid; t < N / 4; t += 512) rowv[t] = __ldcs(&arow[t]);

    #pragma unroll
    for (int t = tid; t < GS; t += 512) sidx[t] = g_idx[b * GS + t];

    if (tid < F / 4) {
        const float4* xrow = (const float4*)(x + ((size_t)b * N + ri) * F);
        float4* xgrow = (float4*)(out + (size_t)B * GS * GS
                                      + ((size_t)b * GS + i) * F);
        xgrow[tid] = xrow[tid];
    }

    __syncthreads();

    // Paired gather: thread t -> columns 2t, 2t+1
    const int2 ip = ((const int2*)sidx)[tid];
    float2 v;
    v.x = row[ip.x];
    v.y = row[ip.y];
    float* orow = out + ((size_t)b * GS + i) * GS;
    ((float2*)orow)[tid] = v;
}

// ---------------------------------------------------------------------------
extern "C" void kernel_launch(void* const* d_in, const int* in_sizes, int n_in,
                              void* d_out, int out_size)
{
    const float* A = (const float*)d_in[0];  // (8,4096,4096) f32
    const float* x = (const float*)d_in[1];  // (8,4096,128)  f32
    float* out = (float*)d_out;              // At2 (8,1024,1024) ++ xg (8,1024,128)

    extract_hist_kernel<<<(B * N) / 256, 256>>>(x);
    select_rank_kernel<<<B, 1024>>>();
    gather_kernel<<<B * GS, 512>>>(A, x, out);
}

// round 11
// speedup vs baseline: 1.3640x; 1.3640x over previous
#include <cuda_runtime.h>
#include <cstdint>

#define B  8
#define N  4096
#define F  128
#define GS 1024

// Final top-k indices, jax order
__device__ int g_idx[B * GS];

__device__ __forceinline__ unsigned int monot(float v) {
    unsigned int u = __float_as_uint(v);
    return (u & 0x80000000u) ? ~u : (u | 0x80000000u); // bigger float -> bigger uint
}

// ---------------------------------------------------------------------------
// scan_hist: find bin containing the `need`-th largest (suffix scan over 256
// bins done by warp 0; 8 bins per lane).
// ---------------------------------------------------------------------------
__device__ __forceinline__ void scan_hist(const unsigned int* hist, unsigned int need,
                                          unsigned int* s_bin, unsigned int* s_above)
{
    const int tid = threadIdx.x;
    if (tid < 32) {
        unsigned int sum = 0;
        #pragma unroll
        for (int j = 0; j < 8; ++j) sum += hist[tid * 8 + j];
        unsigned int acc = sum;
        #pragma unroll
        for (int off = 1; off < 32; off <<= 1) {
            unsigned int t = __shfl_down_sync(0xFFFFFFFFu, acc, off);
            if (tid + off < 32) acc += t;
        }
        unsigned int running = acc - sum;      // strictly above my 8-bin group
        #pragma unroll
        for (int j = 7; j >= 0; --j) {
            unsigned int c = hist[tid * 8 + j];
            if (running < need && need <= running + c) {
                *s_bin = (unsigned int)(tid * 8 + j);
                *s_above = running;
            }
            running += c;
        }
    }
}

// ---------------------------------------------------------------------------
// K1: fully fused per-batch top-k. 8 CTAs x 1024 thr.
//   1. load x[:, :, F-1] (strided), build composite keys in registers
//   2. 256-bin smem histogram of top-8 bits -> threshold bin
//   3. compact threshold-bin candidates, 5 candidate-only radix passes
//      -> exact GS-th largest composite
//   4. compact the GS selected keys, bitonic sort DESCENDING (55 stages)
//   5. write ordered indices: g_idx[b*GS + r] for r = 0..GS-1
// composite = (u << 12) | (4095 - i): larger == earlier in jax order; unique.
// ---------------------------------------------------------------------------
__global__ __launch_bounds__(1024) void select_sort_kernel(const float* __restrict__ x)
{
    __shared__ unsigned long long cand[N];      // 32 KB (worst-case threshold bin)
    __shared__ unsigned long long stage[GS];    // 8 KB, selected keys
    __shared__ unsigned int hist[256];
    __shared__ unsigned int s_bin, s_above, s_m, s_cnt;

    const int b   = blockIdx.x;
    const int tid = threadIdx.x;

    if (tid < 256) hist[tid] = 0;
    if (tid == 0) { s_m = 0; s_cnt = 0; }
    __syncthreads();

    // Load 4 values per thread (MLP-4), build composites, histogram top-8 bits
    unsigned long long comp[4];
    #pragma unroll
    for (int l = 0; l < 4; ++l) {
        const int i = l * 1024 + tid;
        unsigned int u = monot(__ldcs(&x[((size_t)b * N + i) * F + (F - 1)]));
        comp[l] = ((unsigned long long)u << 12) | (unsigned int)(N - 1 - i);
    }
    #pragma unroll
    for (int l = 0; l < 4; ++l)
        atomicAdd(&hist[(unsigned int)(comp[l] >> 36)], 1u);
    __syncthreads();

    scan_hist(hist, GS, &s_bin, &s_above);
    __syncthreads();
    const unsigned int bin1 = s_bin;
    unsigned int need = GS - s_above;

    // Compact threshold-bin candidates
    #pragma unroll
    for (int l = 0; l < 4; ++l) {
        if ((unsigned int)(comp[l] >> 36) == bin1) {
            unsigned int p = atomicAdd(&s_m, 1u);
            cand[p] = comp[l];
        }
    }
    __syncthreads();
    const unsigned int m = s_m;

    // 5 candidate-only radix passes -> exact GS-th largest composite
    unsigned long long prefix = (unsigned long long)bin1 << 36;
    unsigned long long pmask  = 0xFFull << 36;

    #pragma unroll
    for (int pass = 0; pass < 5; ++pass) {
        const int          shift = (pass < 4) ? (28 - 8 * pass) : 0;
        const unsigned int dmask = (pass < 4) ? 0xFFu : 0xFu;

        if (tid < 256) hist[tid] = 0;
        __syncthreads();
        for (unsigned int idx = tid; idx < m; idx += 1024) {
            unsigned long long k = cand[idx];
            if ((k & pmask) == prefix)
                atomicAdd(&hist[(unsigned int)(k >> shift) & dmask], 1u);
        }
        __syncthreads();
        scan_hist(hist, need, &s_bin, &s_above);
        __syncthreads();
        prefix |= ((unsigned long long)s_bin) << shift;
        pmask  |= ((unsigned long long)dmask) << shift;
        need   -= s_above;
        __syncthreads();
    }
    // Selected set: composite >= prefix (exactly GS keys, unique).

    #pragma unroll
    for (int l = 0; l < 4; ++l) {
        if (comp[l] >= prefix) {
            unsigned int p = atomicAdd(&s_cnt, 1u);
            stage[p] = comp[l];
        }
    }
    __syncthreads();

    // Bitonic sort of the GS selected keys, DESCENDING (largest first)
    for (int k = 2; k <= GS; k <<= 1) {
        for (int j = k >> 1; j > 0; j >>= 1) {
            const int ixj = tid ^ j;
            if (ixj > tid) {
                unsigned long long a = stage[tid];
                unsigned long long c = stage[ixj];
                const bool up = ((tid & k) == 0);
                if ((a < c) == up) { stage[tid] = c; stage[ixj] = a; }
            }
            __syncthreads();
        }
    }

    g_idx[b * GS + tid] = (N - 1) - (int)(stage[tid] & 0xFFFull);
}

// ---------------------------------------------------------------------------
// K2 (R8-proven): one CTA per output row (b, i).
//   - coalesced float4 streaming load of A[b, idx[i], :] (16KB) into smem
//   - smem gather of 1024 selected columns -> At2 row
//   - warp 0 copies x[b, idx[i], :] (512B) -> xg row
// ---------------------------------------------------------------------------
__global__ __launch_bounds__(512) void gather_kernel(const float* __restrict__ A,
                                                     const float* __restrict__ x,
                                                     float* __restrict__ out)
{
    __shared__ float row[N];        // 16 KB
    __shared__ int   sidx[GS];      // 4 KB

    const int bi  = blockIdx.x;
    const int b   = bi >> 10;
    const int i   = bi & (GS - 1);
    const int tid = threadIdx.x;

    const int ri = g_idx[b * GS + i];

    const float4* arow = (const float4*)(A + ((size_t)b * N + ri) * N);
    float4* rowv = (float4*)row;
    #pragma unroll
    for (int t = tid; t < N / 4; t += 512) rowv[t] = __ldcs(&arow[t]);

    #pragma unroll
    for (int t = tid; t < GS; t += 512) sidx[t] = g_idx[b * GS + t];

    if (tid < F / 4) {
        const float4* xrow = (const float4*)(x + ((size_t)b * N + ri) * F);
        float4* xgrow = (float4*)(out + (size_t)B * GS * GS
                                      + ((size_t)b * GS + i) * F);
        xgrow[tid] = xrow[tid];
    }

    __syncthreads();

    float* orow = out + ((size_t)b * GS + i) * GS;
    #pragma unroll
    for (int t = tid; t < GS; t += 512) orow[t] = row[sidx[t]];
}

// ---------------------------------------------------------------------------
extern "C" void kernel_launch(void* const* d_in, const int* in_sizes, int n_in,
                              void* d_out, int out_size)
{
    const float* A = (const float*)d_in[0];  // (8,4096,4096) f32
    const float* x = (const float*)d_in[1];  // (8,4096,128)  f32
    float* out = (float*)d_out;              // At2 (8,1024,1024) ++ xg (8,1024,128)

    select_sort_kernel<<<B, 1024>>>(x);
    gather_kernel<<<B * GS, 512>>>(A, x, out);
}